// round 1
// baseline (speedup 1.0000x reference)
#include <cuda_runtime.h>

#define T_DIM 4096
#define K_DIM 16384
#define HCN 4
#define N_OUT 24
#define NP 12          // float2 pairs across N
#define MB 64          // rows per CTA
#define KSPLIT 8
#define KCHUNK (K_DIM / KSPLIT)   // 2048
#define KT 1024        // K tile staged in smem
#define RT 4           // rows per thread
#define KTH 16         // k-threads per row group
#define NTHREADS 256
#define KPAD (KT + 2)  // float2 stride pad

// Scratch (device globals; no allocation allowed)
__device__ float2 g_hpart[KSPLIT][T_DIM][NP];
__device__ float  g_sspart[KSPLIT][T_DIM];

using u64 = unsigned long long;

__device__ __forceinline__ u64 fma2(u64 a, u64 b, u64 c) {
    u64 d;
    asm("fma.rn.f32x2 %0, %1, %2, %3;" : "=l"(d) : "l"(a), "l"(b), "l"(c));
    return d;
}
__device__ __forceinline__ u64 pack2(float x) {
    u64 d;
    asm("mov.b64 %0, {%1, %1};" : "=l"(d) : "f"(x));
    return d;
}
__device__ __forceinline__ float2 u2f(u64 a) {
    float2 f;
    asm("mov.b64 {%0, %1}, %2;" : "=f"(f.x), "=f"(f.y) : "l"(a));
    return f;
}

// ---------------------------------------------------------------------------
// Kernel A: h_part[bk][row][0:24) = x[row, kchunk] @ W[kchunk, 0:24)
//           ss_part[bk][row]      = sum(x[row, kchunk]^2)
// Register-blocked: each thread owns 4 rows x 12 f32x2 (N-paired) accumulators.
// ---------------------------------------------------------------------------
extern "C" __global__ void __launch_bounds__(NTHREADS, 1)
mhc_gemm_kernel(const float* __restrict__ x, const float* __restrict__ w) {
    extern __shared__ char smem[];
    u64* sw = (u64*)smem;  // weight pairs: [NP][KPAD] float2

    const int tid = threadIdx.x;
    const int bm = blockIdx.x;
    const int bk = blockIdx.y;
    const int g   = tid >> 4;    // row group 0..15
    const int kth = tid & 15;    // k-thread 0..15 (lane-consecutive k)
    const int row0 = bm * MB;
    const int rbase = row0 + g * RT;

    const float* xr0 = x + (size_t)(rbase + 0) * K_DIM;
    const float* xr1 = x + (size_t)(rbase + 1) * K_DIM;
    const float* xr2 = x + (size_t)(rbase + 2) * K_DIM;
    const float* xr3 = x + (size_t)(rbase + 3) * K_DIM;

    u64 acc[RT][NP];
    float ss0 = 0.f, ss1 = 0.f, ss2 = 0.f, ss3 = 0.f;
#pragma unroll
    for (int r = 0; r < RT; r++)
#pragma unroll
        for (int p = 0; p < NP; p++) acc[r][p] = 0ull;

    for (int tile = 0; tile < KCHUNK / KT; tile++) {
        const int k0 = bk * KCHUNK + tile * KT;

        // Stage weight tile: W[k0..k0+KT)[0:24) -> sw[pair][k] (float2 pairs)
#pragma unroll
        for (int it = 0; it < (KT * 6) / NTHREADS; it++) {
            int idx = tid + NTHREADS * it;
            int kk = idx / 6, q = idx % 6;
            float4 v = *(const float4*)(w + (size_t)(k0 + kk) * N_OUT + q * 4);
            ((float2*)sw)[(2 * q + 0) * KPAD + kk] = make_float2(v.x, v.y);
            ((float2*)sw)[(2 * q + 1) * KPAD + kk] = make_float2(v.z, v.w);
        }
        __syncthreads();

#pragma unroll 2
        for (int i = 0; i < KT / KTH; i++) {
            const int k = i * KTH + kth;  // lanes 0..15 consecutive -> coalesced
            float x0 = __ldcs(xr0 + k0 + k);
            float x1 = __ldcs(xr1 + k0 + k);
            float x2 = __ldcs(xr2 + k0 + k);
            float x3 = __ldcs(xr3 + k0 + k);
            u64 wp[NP];
#pragma unroll
            for (int p = 0; p < NP; p++) wp[p] = sw[p * KPAD + k];
            u64 xx0 = pack2(x0), xx1 = pack2(x1), xx2 = pack2(x2), xx3 = pack2(x3);
#pragma unroll
            for (int p = 0; p < NP; p++) {
                acc[0][p] = fma2(xx0, wp[p], acc[0][p]);
                acc[1][p] = fma2(xx1, wp[p], acc[1][p]);
                acc[2][p] = fma2(xx2, wp[p], acc[2][p]);
                acc[3][p] = fma2(xx3, wp[p], acc[3][p]);
            }
            ss0 = fmaf(x0, x0, ss0);
            ss1 = fmaf(x1, x1, ss1);
            ss2 = fmaf(x2, x2, ss2);
            ss3 = fmaf(x3, x3, ss3);
        }
        __syncthreads();
    }

    // Cross-thread (k-thread) reduction via smem (overlays weight buffer)
    float2* red = (float2*)smem;                                   // [MB][KTH][NP]
    float* ssred = (float*)(smem + (size_t)MB * KTH * NP * 8);     // [MB][KTH]
    {
        float ssl[RT] = {ss0, ss1, ss2, ss3};
#pragma unroll
        for (int r = 0; r < RT; r++) {
            int rl = g * RT + r;
#pragma unroll
            for (int p = 0; p < NP; p++)
                red[(rl * KTH + kth) * NP + p] = u2f(acc[r][p]);
            ssred[rl * KTH + kth] = ssl[r];
        }
    }
    __syncthreads();

    // 64 rows x 12 pairs = 768 columns; 256 threads x 3 each
#pragma unroll
    for (int j = 0; j < 3; j++) {
        int col = tid * 3 + j;
        int rl = col / NP, p = col % NP;
        float2 s = make_float2(0.f, 0.f);
#pragma unroll
        for (int t = 0; t < KTH; t++) {
            float2 a = red[(rl * KTH + t) * NP + p];
            s.x += a.x;
            s.y += a.y;
        }
        g_hpart[bk][row0 + rl][p] = s;
    }
    if (tid < MB) {
        float s = 0.f;
#pragma unroll
        for (int t = 0; t < KTH; t++) s += ssred[tid * KTH + t];
        g_sspart[bk][row0 + tid] = s;
    }
}

// ---------------------------------------------------------------------------
// Kernel B: reduce K-split partials, activations, Sinkhorn (early-exit, cap
// 400 which matches the reference's MAX_IT*MAX_IT), write outputs.
// Output layout: [h_pre (T,4)] [h_post (T,4)] [h_res (T,4,4)] concatenated.
// ---------------------------------------------------------------------------
extern "C" __global__ void __launch_bounds__(256)
mhc_finish_kernel(const float* __restrict__ bias, const float* __restrict__ alpha,
                  float* __restrict__ out) {
    int row = blockIdx.x * blockDim.x + threadIdx.x;
    if (row >= T_DIM) return;

    float h[N_OUT];
#pragma unroll
    for (int p = 0; p < NP; p++) {
        float sx = 0.f, sy = 0.f;
#pragma unroll
        for (int c = 0; c < KSPLIT; c++) {
            float2 a = g_hpart[c][row][p];
            sx += a.x;
            sy += a.y;
        }
        h[2 * p] = sx;
        h[2 * p + 1] = sy;
    }
    float ss = 0.f;
#pragma unroll
    for (int c = 0; c < KSPLIT; c++) ss += g_sspart[c][row];

    float r_inv = rsqrtf(ss * (1.0f / K_DIM));
    float a0 = alpha[0], a1 = alpha[1], a2 = alpha[2];

    float pre[HCN], post[HCN], H[HCN][HCN];
#pragma unroll
    for (int n = 0; n < HCN; n++) {
        float z0 = fmaf(r_inv * a0, h[n], bias[n]);
        pre[n] = 1.f / (1.f + __expf(-z0));
        float z1 = fmaf(r_inv * a1, h[HCN + n], bias[HCN + n]);
        post[n] = 2.f / (1.f + __expf(-z1));
    }
#pragma unroll
    for (int i = 0; i < HCN; i++)
#pragma unroll
        for (int j = 0; j < HCN; j++) {
            float z = fmaf(r_inv * a2, h[8 + 4 * i + j], bias[8 + 4 * i + j]);
            H[i][j] = __expf(z);
        }

    const float EPSV = 1e-12f;
    float u[4] = {1.f, 1.f, 1.f, 1.f}, v[4] = {1.f, 1.f, 1.f, 1.f};
    for (int it = 0; it < 400; it++) {
        float nu[4];
#pragma unroll
        for (int i = 0; i < 4; i++) {
            float uv = H[i][0] * v[0] + H[i][1] * v[1] + H[i][2] * v[2] + H[i][3] * v[3];
            nu[i] = __fdividef(1.f, uv + EPSV);
        }
        float maxrel = 0.f;
#pragma unroll
        for (int j = 0; j < 4; j++) {
            float vu = H[0][j] * nu[0] + H[1][j] * nu[1] + H[2][j] * nu[2] + H[3][j] * nu[3];
            float nv = __fdividef(1.f, vu + EPSV);
            float rel = fabsf(nv - v[j]) * __fdividef(1.f, fabsf(nv) + 1e-30f);
            maxrel = fmaxf(maxrel, rel);
            v[j] = nv;
        }
        u[0] = nu[0]; u[1] = nu[1]; u[2] = nu[2]; u[3] = nu[3];
        if (maxrel < 1e-6f) break;   // converged: further iterations are no-ops
    }

    // Write outputs (all vectorized float4, fully coalesced within region)
    ((float4*)out)[row] = make_float4(pre[0], pre[1], pre[2], pre[3]);
    ((float4*)(out + (size_t)T_DIM * HCN))[row] =
        make_float4(post[0], post[1], post[2], post[3]);
    float4* res = (float4*)(out + 2 * (size_t)T_DIM * HCN + (size_t)row * 16);
#pragma unroll
    for (int i = 0; i < 4; i++) {
        res[i] = make_float4(u[i] * H[i][0] * v[0], u[i] * H[i][1] * v[1],
                             u[i] * H[i][2] * v[2], u[i] * H[i][3] * v[3]);
    }
}

// ---------------------------------------------------------------------------
#define SMEM_BYTES ((size_t)MB * KTH * NP * 8 + (size_t)MB * KTH * 4)  // 102400
// (weight staging needs NP*KPAD*8 = 98496; reduction overlay needs 102400)

extern "C" void kernel_launch(void* const* d_in, const int* in_sizes, int n_in,
                              void* d_out, int out_size) {
    const float* x = (const float*)d_in[0];
    const float* w = (const float*)d_in[1];
    const float* bias = (const float*)d_in[2];
    const float* alpha = (const float*)d_in[3];
    float* out = (float*)d_out;

    cudaFuncSetAttribute(mhc_gemm_kernel,
                         cudaFuncAttributeMaxDynamicSharedMemorySize,
                         (int)SMEM_BYTES);

    dim3 grid(T_DIM / MB, KSPLIT);
    mhc_gemm_kernel<<<grid, NTHREADS, SMEM_BYTES>>>(x, w);
    mhc_finish_kernel<<<T_DIM / 256, 256>>>(bias, alpha, out);
}

// round 2
// speedup vs baseline: 1.0128x; 1.0128x over previous
#include <cuda_runtime.h>

#define T_DIM 4096
#define K_DIM 16384
#define HCN 4
#define N_OUT 24
#define NP 12          // float2 pairs across N
#define MB 64          // rows per CTA
#define KSPLIT 8
#define KCHUNK (K_DIM / KSPLIT)   // 2048
#define KT 1024        // K tile staged in smem
#define RT 4           // rows per thread
#define KTH 16         // k-threads per row group
#define NTHREADS 256
#define BIGS (KT / 64)            // 16 big-iters per tile (64 k each)
#define NTILES (KCHUNK / KT)      // 2

// Scratch (device globals; no allocation allowed)
__device__ float2 g_hpart[KSPLIT][T_DIM][NP];
__device__ float  g_sspart[KSPLIT][T_DIM];

using u64 = unsigned long long;

__device__ __forceinline__ u64 fma2(u64 a, u64 b, u64 c) {
    u64 d;
    asm("fma.rn.f32x2 %0, %1, %2, %3;" : "=l"(d) : "l"(a), "l"(b), "l"(c));
    return d;
}
__device__ __forceinline__ u64 pack2(float x) {
    u64 d;
    asm("mov.b64 %0, {%1, %1};" : "=l"(d) : "f"(x));
    return d;
}
__device__ __forceinline__ float2 u2f(u64 a) {
    float2 f;
    asm("mov.b64 {%0, %1}, %2;" : "=f"(f.x), "=f"(f.y) : "l"(a));
    return f;
}
__device__ __forceinline__ float f4get(const float4& v, int s) {
    return s == 0 ? v.x : (s == 1 ? v.y : (s == 2 ? v.z : v.w));
}

// ---------------------------------------------------------------------------
// Kernel A: h_part[bk][row][0:24) = x[row, kchunk] @ W[kchunk, 0:24)
//           ss_part[bk][row]      = sum(x[row, kchunk]^2)
// x loaded as float4 with one-iteration-ahead prefetch; weights staged in
// smem with phase-swizzled layout sw[p][k&3][k>>2] so the stride-4 k access
// from float4 substeps is a conflict-free LDS.64.
// ---------------------------------------------------------------------------
extern "C" __global__ void __launch_bounds__(NTHREADS, 1)
mhc_gemm_kernel(const float* __restrict__ x, const float* __restrict__ w) {
    extern __shared__ char smem[];
    u64* sw = (u64*)smem;  // [NP][4][256] float2, phase-swizzled

    const int tid = threadIdx.x;
    const int bm = blockIdx.x;
    const int bk = blockIdx.y;
    const int g   = tid >> 4;    // row group 0..15
    const int kth = tid & 15;    // k-thread 0..15
    const int row0 = bm * MB;
    const int rbase = row0 + g * RT;

    // float4 base pointers for this thread's rows within this k-chunk
    const float4* xb0 = (const float4*)(x + (size_t)(rbase + 0) * K_DIM) + bk * (KCHUNK / 4);
    const float4* xb1 = (const float4*)(x + (size_t)(rbase + 1) * K_DIM) + bk * (KCHUNK / 4);
    const float4* xb2 = (const float4*)(x + (size_t)(rbase + 2) * K_DIM) + bk * (KCHUNK / 4);
    const float4* xb3 = (const float4*)(x + (size_t)(rbase + 3) * K_DIM) + bk * (KCHUNK / 4);

    u64 acc[RT][NP];
    float ss0 = 0.f, ss1 = 0.f, ss2 = 0.f, ss3 = 0.f;
#pragma unroll
    for (int r = 0; r < RT; r++)
#pragma unroll
        for (int p = 0; p < NP; p++) acc[r][p] = 0ull;

    // Prefetch first vectors
    float4 n0 = __ldcs(xb0 + kth);
    float4 n1 = __ldcs(xb1 + kth);
    float4 n2 = __ldcs(xb2 + kth);
    float4 n3 = __ldcs(xb3 + kth);

    for (int tile = 0; tile < NTILES; tile++) {
        const int k0 = bk * KCHUNK + tile * KT;

        // Stage weight tile: W[k0..k0+KT)[0:24) -> phase-swizzled float2
#pragma unroll
        for (int it = 0; it < (KT * 6) / NTHREADS; it++) {
            int idx = tid + NTHREADS * it;
            int kk = idx / 6, q = idx % 6;
            float4 v = *(const float4*)(w + (size_t)(k0 + kk) * N_OUT + q * 4);
            int base = (kk & 3) * 256 + (kk >> 2);
            ((float2*)sw)[(2 * q + 0) * 1024 + base] = make_float2(v.x, v.y);
            ((float2*)sw)[(2 * q + 1) * 1024 + base] = make_float2(v.z, v.w);
        }
        __syncthreads();

        for (int i = 0; i < BIGS; i++) {
            float4 c0 = n0, c1 = n1, c2 = n2, c3 = n3;
            // Prefetch next big-iter (possibly crossing into next tile);
            // clamp at chunk end (redundant reload, harmless).
            int gnext = tile * BIGS + i + 1;
            if (gnext > NTILES * BIGS - 1) gnext = NTILES * BIGS - 1;
            int goff = gnext * 16 + kth;
            n0 = __ldcs(xb0 + goff);
            n1 = __ldcs(xb1 + goff);
            n2 = __ldcs(xb2 + goff);
            n3 = __ldcs(xb3 + goff);

            const int kb = i * 16 + kth;  // k>>2 index within tile
#pragma unroll
            for (int s = 0; s < 4; s++) {
                u64 wp[NP];
#pragma unroll
                for (int p = 0; p < NP; p++)
                    wp[p] = sw[p * 1024 + s * 256 + kb];
                float xs0 = f4get(c0, s), xs1 = f4get(c1, s);
                float xs2 = f4get(c2, s), xs3 = f4get(c3, s);
                u64 X0 = pack2(xs0), X1 = pack2(xs1);
                u64 X2 = pack2(xs2), X3 = pack2(xs3);
#pragma unroll
                for (int p = 0; p < NP; p++) {
                    acc[0][p] = fma2(X0, wp[p], acc[0][p]);
                    acc[1][p] = fma2(X1, wp[p], acc[1][p]);
                    acc[2][p] = fma2(X2, wp[p], acc[2][p]);
                    acc[3][p] = fma2(X3, wp[p], acc[3][p]);
                }
                ss0 = fmaf(xs0, xs0, ss0);
                ss1 = fmaf(xs1, xs1, ss1);
                ss2 = fmaf(xs2, xs2, ss2);
                ss3 = fmaf(xs3, xs3, ss3);
            }
        }
        __syncthreads();
    }

    // Cross-thread (k-thread) reduction via smem (overlays weight buffer)
    float2* red = (float2*)smem;                                   // [MB][KTH][NP]
    float* ssred = (float*)(smem + (size_t)MB * KTH * NP * 8);     // [MB][KTH]
    {
        float ssl[RT] = {ss0, ss1, ss2, ss3};
#pragma unroll
        for (int r = 0; r < RT; r++) {
            int rl = g * RT + r;
#pragma unroll
            for (int p = 0; p < NP; p++)
                red[(rl * KTH + kth) * NP + p] = u2f(acc[r][p]);
            ssred[rl * KTH + kth] = ssl[r];
        }
    }
    __syncthreads();

    // 64 rows x 12 pairs = 768 columns; 256 threads x 3 each
#pragma unroll
    for (int j = 0; j < 3; j++) {
        int col = tid * 3 + j;
        int rl = col / NP, p = col % NP;
        float2 s = make_float2(0.f, 0.f);
#pragma unroll
        for (int t = 0; t < KTH; t++) {
            float2 a = red[(rl * KTH + t) * NP + p];
            s.x += a.x;
            s.y += a.y;
        }
        g_hpart[bk][row0 + rl][p] = s;
    }
    if (tid < MB) {
        float s = 0.f;
#pragma unroll
        for (int t = 0; t < KTH; t++) s += ssred[tid * KTH + t];
        g_sspart[bk][row0 + tid] = s;
    }
}

// ---------------------------------------------------------------------------
// Kernel B: reduce K-split partials, activations, Sinkhorn (early-exit, cap
// 400 = reference's MAX_IT*MAX_IT), write outputs.
// Grid 128 x 32 threads: one warp per SM -> 128 SMs active (was 16).
// ---------------------------------------------------------------------------
extern "C" __global__ void __launch_bounds__(32)
mhc_finish_kernel(const float* __restrict__ bias, const float* __restrict__ alpha,
                  float* __restrict__ out) {
    int row = blockIdx.x * 32 + threadIdx.x;

    float h[N_OUT];
#pragma unroll
    for (int p = 0; p < NP; p++) {
        float sx = 0.f, sy = 0.f;
#pragma unroll
        for (int c = 0; c < KSPLIT; c++) {
            float2 a = g_hpart[c][row][p];
            sx += a.x;
            sy += a.y;
        }
        h[2 * p] = sx;
        h[2 * p + 1] = sy;
    }
    float ss = 0.f;
#pragma unroll
    for (int c = 0; c < KSPLIT; c++) ss += g_sspart[c][row];

    float r_inv = rsqrtf(ss * (1.0f / K_DIM));
    float a0 = alpha[0], a1 = alpha[1], a2 = alpha[2];

    float pre[HCN], post[HCN], H[HCN][HCN];
#pragma unroll
    for (int n = 0; n < HCN; n++) {
        float z0 = fmaf(r_inv * a0, h[n], bias[n]);
        pre[n] = 1.f / (1.f + __expf(-z0));
        float z1 = fmaf(r_inv * a1, h[HCN + n], bias[HCN + n]);
        post[n] = 2.f / (1.f + __expf(-z1));
    }
#pragma unroll
    for (int i = 0; i < HCN; i++)
#pragma unroll
        for (int j = 0; j < HCN; j++) {
            float z = fmaf(r_inv * a2, h[8 + 4 * i + j], bias[8 + 4 * i + j]);
            H[i][j] = __expf(z);
        }

    const float EPSV = 1e-12f;
    float u[4] = {1.f, 1.f, 1.f, 1.f}, v[4] = {1.f, 1.f, 1.f, 1.f};
    for (int it = 0; it < 400; it++) {
        float nu[4];
#pragma unroll
        for (int i = 0; i < 4; i++) {
            float uv = fmaf(H[i][3], v[3],
                       fmaf(H[i][2], v[2],
                       fmaf(H[i][1], v[1],
                       fmaf(H[i][0], v[0], EPSV))));
            nu[i] = __fdividef(1.f, uv);
        }
        float maxrel = 0.f;
#pragma unroll
        for (int j = 0; j < 4; j++) {
            float vu = fmaf(H[3][j], nu[3],
                       fmaf(H[2][j], nu[2],
                       fmaf(H[1][j], nu[1],
                       fmaf(H[0][j], nu[0], EPSV))));
            float nv = __fdividef(1.f, vu);
            float rel = fabsf(nv - v[j]) * __fdividef(1.f, fabsf(nv) + 1e-30f);
            maxrel = fmaxf(maxrel, rel);
            v[j] = nv;
        }
        u[0] = nu[0]; u[1] = nu[1]; u[2] = nu[2]; u[3] = nu[3];
        if (maxrel < 1e-6f) break;   // converged: further iterations are no-ops
    }

    // Write outputs (all vectorized float4, fully coalesced within region)
    ((float4*)out)[row] = make_float4(pre[0], pre[1], pre[2], pre[3]);
    ((float4*)(out + (size_t)T_DIM * HCN))[row] =
        make_float4(post[0], post[1], post[2], post[3]);
    float4* res = (float4*)(out + 2 * (size_t)T_DIM * HCN + (size_t)row * 16);
#pragma unroll
    for (int i = 0; i < 4; i++) {
        res[i] = make_float4(u[i] * H[i][0] * v[0], u[i] * H[i][1] * v[1],
                             u[i] * H[i][2] * v[2], u[i] * H[i][3] * v[3]);
    }
}

// ---------------------------------------------------------------------------
#define SMEM_BYTES ((size_t)MB * KTH * NP * 8 + (size_t)MB * KTH * 4)  // 102400
// (weight staging needs NP*1024*8 = 98304; reduction overlay needs 102400)

extern "C" void kernel_launch(void* const* d_in, const int* in_sizes, int n_in,
                              void* d_out, int out_size) {
    const float* x = (const float*)d_in[0];
    const float* w = (const float*)d_in[1];
    const float* bias = (const float*)d_in[2];
    const float* alpha = (const float*)d_in[3];
    float* out = (float*)d_out;

    cudaFuncSetAttribute(mhc_gemm_kernel,
                         cudaFuncAttributeMaxDynamicSharedMemorySize,
                         (int)SMEM_BYTES);

    dim3 grid(T_DIM / MB, KSPLIT);
    mhc_gemm_kernel<<<grid, NTHREADS, SMEM_BYTES>>>(x, w);
    mhc_finish_kernel<<<T_DIM / 32, 32>>>(bias, alpha, out);
}

// round 4
// speedup vs baseline: 1.1857x; 1.1707x over previous
#include <cuda_runtime.h>

#define T_DIM 4096
#define K_DIM 16384
#define HCN 4
#define N_OUT 24
#define NP 12          // float2 pairs across N
#define MB 32          // rows per CTA
#define KSPLIT 8
#define KCHUNK (K_DIM / KSPLIT)   // 2048
#define KT 512         // K tile staged in smem
#define NTILES (KCHUNK / KT)      // 4
#define RT 4           // rows per warp (held in regs, N-split across halves)
#define NTHREADS 256
#define PPAD 13        // padded pair stride for reduction (26 banks, conflict-free)

// Scratch (device globals; no allocation allowed)
// Transposed: [split][pair][row] so finish-kernel reads are coalesced.
__device__ float2 g_hpart[KSPLIT][NP][T_DIM];
__device__ float  g_sspart[KSPLIT][T_DIM];

using u64 = unsigned long long;

__device__ __forceinline__ u64 fma2(u64 a, u64 b, u64 c) {
    u64 d;
    asm("fma.rn.f32x2 %0, %1, %2, %3;" : "=l"(d) : "l"(a), "l"(b), "l"(c));
    return d;
}
__device__ __forceinline__ u64 pack2(float x) {
    u64 d;
    asm("mov.b64 %0, {%1, %1};" : "=l"(d) : "f"(x));
    return d;
}
__device__ __forceinline__ float2 u2f(u64 a) {
    float2 f;
    asm("mov.b64 {%0, %1}, %2;" : "=f"(f.x), "=f"(f.y) : "l"(a));
    return f;
}
__device__ __forceinline__ float frcp(float a) {
    float r;
    asm("rcp.approx.f32 %0, %1;" : "=f"(r) : "f"(a));
    return r;
}
__device__ __forceinline__ float f4get(const float4& v, int s) {
    return s == 0 ? v.x : (s == 1 ? v.y : (s == 2 ? v.z : v.w));
}

// ---------------------------------------------------------------------------
// Kernel A: h_part[bk][p][row] = x[row, kchunk] @ W[kchunk, pair p)
//           ss_part[bk][row]   = sum(x[row, kchunk]^2)
// Warp layout: lane = half*16 + kth. Each warp owns RT=4 rows; lanes 0-15
// accumulate output pairs 0-5, lanes 16-31 pairs 6-11 (same rows, same k).
// Halves acc regs (48 u64) -> 2 CTAs/SM, 4 warps/SMSP.
// ---------------------------------------------------------------------------
extern "C" __global__ void __launch_bounds__(NTHREADS, 2)
mhc_gemm_kernel(const float* __restrict__ x, const float* __restrict__ w) {
    extern __shared__ char smem[];
    u64* sw = (u64*)smem;  // [NP][4 phases][KT/4] u64 (float2 pairs)

    const int tid = threadIdx.x;
    const int wid = tid >> 5;          // warp 0..7
    const int half = (tid >> 4) & 1;   // N-half
    const int kth = tid & 15;          // k lane
    const int p6 = half * 6;           // pair offset for this half
    const int bm = blockIdx.x;
    const int bk = blockIdx.y;
    const int row0 = bm * MB;
    const int rbase = row0 + wid * RT;

    const float4* xb0 = (const float4*)(x + (size_t)(rbase + 0) * K_DIM);
    const float4* xb1 = (const float4*)(x + (size_t)(rbase + 1) * K_DIM);
    const float4* xb2 = (const float4*)(x + (size_t)(rbase + 2) * K_DIM);
    const float4* xb3 = (const float4*)(x + (size_t)(rbase + 3) * K_DIM);

    u64 acc[RT][6];
    float ss0 = 0.f, ss1 = 0.f, ss2 = 0.f, ss3 = 0.f;
#pragma unroll
    for (int r = 0; r < RT; r++)
#pragma unroll
        for (int p = 0; p < 6; p++) acc[r][p] = 0ull;

    for (int tile = 0; tile < NTILES; tile++) {
        const int k0 = bk * KCHUNK + tile * KT;

        // Stage W[k0..k0+KT)[0:24) -> sw[pair][k&3][k>>2]
#pragma unroll
        for (int it = 0; it < (KT * 6) / NTHREADS; it++) {
            int idx = tid + NTHREADS * it;
            int kk = idx / 6, q = idx % 6;
            float4 v = *(const float4*)(w + (size_t)(k0 + kk) * N_OUT + q * 4);
            int base = (kk & 3) * (KT / 4) + (kk >> 2);
            ((float2*)sw)[(2 * q + 0) * KT + base] = make_float2(v.x, v.y);
            ((float2*)sw)[(2 * q + 1) * KT + base] = make_float2(v.z, v.w);
        }
        __syncthreads();

        const int kf4base = (k0 >> 2);
#pragma unroll 2
        for (int i = 0; i < KT / 64; i++) {
            const int kf4 = i * 16 + kth;   // float4 index within tile [0, KT/4)
            float4 c0 = __ldcs(xb0 + kf4base + kf4);
            float4 c1 = __ldcs(xb1 + kf4base + kf4);
            float4 c2 = __ldcs(xb2 + kf4base + kf4);
            float4 c3 = __ldcs(xb3 + kf4base + kf4);
#pragma unroll
            for (int s = 0; s < 4; s++) {
                u64 wp[6];
#pragma unroll
                for (int p = 0; p < 6; p++)
                    wp[p] = sw[(p6 + p) * KT + s * (KT / 4) + kf4];
                float xs0 = f4get(c0, s), xs1 = f4get(c1, s);
                float xs2 = f4get(c2, s), xs3 = f4get(c3, s);
                u64 X0 = pack2(xs0), X1 = pack2(xs1);
                u64 X2 = pack2(xs2), X3 = pack2(xs3);
#pragma unroll
                for (int p = 0; p < 6; p++) {
                    acc[0][p] = fma2(X0, wp[p], acc[0][p]);
                    acc[1][p] = fma2(X1, wp[p], acc[1][p]);
                    acc[2][p] = fma2(X2, wp[p], acc[2][p]);
                    acc[3][p] = fma2(X3, wp[p], acc[3][p]);
                }
                ss0 = fmaf(xs0, xs0, ss0);
                ss1 = fmaf(xs1, xs1, ss1);
                ss2 = fmaf(xs2, xs2, ss2);
                ss3 = fmaf(xs3, xs3, ss3);
            }
        }
        __syncthreads();
    }

    // Cross-kth reduction via smem (overlays weight buffer).
    // red: [MB rows][16 kth][PPAD pairs] float2 (PPAD=13 -> conflict-free)
    float2* red = (float2*)smem;
    float* ssred = (float*)(smem + (size_t)MB * 16 * PPAD * 8);  // [MB][16]
    {
        float ssl[RT] = {ss0, ss1, ss2, ss3};
#pragma unroll
        for (int r = 0; r < RT; r++) {
            int rl = wid * RT + r;
#pragma unroll
            for (int p = 0; p < 6; p++)
                red[((size_t)rl * 16 + kth) * PPAD + p6 + p] = u2f(acc[r][p]);
            if (half == 0) ssred[rl * 16 + kth] = ssl[r];
        }
    }
    __syncthreads();

    // 32 rows x 12 pairs = 384 columns; sum over 16 kth
#pragma unroll
    for (int j = 0; j < 2; j++) {
        int col = j * NTHREADS + tid;
        if (col < MB * NP) {
            int p = col >> 5, rl = col & 31;   // lanes consecutive in rl -> coalesced
            float sx = 0.f, sy = 0.f;
#pragma unroll
            for (int t = 0; t < 16; t++) {
                float2 a = red[((size_t)rl * 16 + t) * PPAD + p];
                sx += a.x;
                sy += a.y;
            }
            g_hpart[bk][p][row0 + rl] = make_float2(sx, sy);
        }
    }
    if (tid < MB) {
        float s = 0.f;
#pragma unroll
        for (int t = 0; t < 16; t++) s += ssred[tid * 16 + t];
        g_sspart[bk][row0 + tid] = s;
    }
}

// ---------------------------------------------------------------------------
// Kernel B: reduce K-split partials, activations, Sinkhorn, write outputs.
// rcp.approx only (8 MUFU/iter), convergence checked every 8 iterations via
// multiply-compare (no MUFU, branch cost amortized 8x). Cap 400 = MAX_IT^2.
// ---------------------------------------------------------------------------
extern "C" __global__ void __launch_bounds__(32)
mhc_finish_kernel(const float* __restrict__ bias, const float* __restrict__ alpha,
                  float* __restrict__ out) {
    int row = blockIdx.x * 32 + threadIdx.x;

    float h[N_OUT];
#pragma unroll
    for (int p = 0; p < NP; p++) {
        float sx = 0.f, sy = 0.f;
#pragma unroll
        for (int c = 0; c < KSPLIT; c++) {
            float2 a = g_hpart[c][p][row];   // lanes consecutive rows -> coalesced
            sx += a.x;
            sy += a.y;
        }
        h[2 * p] = sx;
        h[2 * p + 1] = sy;
    }
    float ss = 0.f;
#pragma unroll
    for (int c = 0; c < KSPLIT; c++) ss += g_sspart[c][row];

    float r_inv = rsqrtf(ss * (1.0f / K_DIM));
    float a0 = alpha[0], a1 = alpha[1], a2 = alpha[2];

    float pre[HCN], post[HCN], H[HCN][HCN];
#pragma unroll
    for (int n = 0; n < HCN; n++) {
        float z0 = fmaf(r_inv * a0, h[n], bias[n]);
        pre[n] = 1.f / (1.f + __expf(-z0));
        float z1 = fmaf(r_inv * a1, h[HCN + n], bias[HCN + n]);
        post[n] = 2.f / (1.f + __expf(-z1));
    }
#pragma unroll
    for (int i = 0; i < HCN; i++)
#pragma unroll
        for (int j = 0; j < HCN; j++) {
            float z = fmaf(r_inv * a2, h[8 + 4 * i + j], bias[8 + 4 * i + j]);
            H[i][j] = __expf(z);
        }

    const float EPSV = 1e-12f;
    float u[4] = {1.f, 1.f, 1.f, 1.f}, v[4] = {1.f, 1.f, 1.f, 1.f};
    for (int o = 0; o < 50; o++) {          // 50 blocks x 8 iters = 400 max
        float vp0 = v[0], vp1 = v[1], vp2 = v[2], vp3 = v[3];
#pragma unroll
        for (int s = 0; s < 8; s++) {
            float nu[4];
#pragma unroll
            for (int i = 0; i < 4; i++) {
                float uv = fmaf(H[i][3], v[3],
                           fmaf(H[i][2], v[2],
                           fmaf(H[i][1], v[1],
                           fmaf(H[i][0], v[0], EPSV))));
                nu[i] = frcp(uv);
            }
#pragma unroll
            for (int j = 0; j < 4; j++) {
                float vu = fmaf(H[3][j], nu[3],
                           fmaf(H[2][j], nu[2],
                           fmaf(H[1][j], nu[1],
                           fmaf(H[0][j], nu[0], EPSV))));
                v[j] = frcp(vu);
            }
            u[0] = nu[0]; u[1] = nu[1]; u[2] = nu[2]; u[3] = nu[3];
        }
        // converged if |v - v_prev8| <= 1e-6 * |v| for all 4 (no divides)
        float m = fabsf(v[0] - vp0) - 1e-6f * fabsf(v[0]);
        m = fmaxf(m, fabsf(v[1] - vp1) - 1e-6f * fabsf(v[1]));
        m = fmaxf(m, fabsf(v[2] - vp2) - 1e-6f * fabsf(v[2]));
        m = fmaxf(m, fabsf(v[3] - vp3) - 1e-6f * fabsf(v[3]));
        if (m <= 0.f) break;
    }

    // Outputs: [h_pre (T,4)] [h_post (T,4)] [h_res (T,4,4)], all float4 stores
    ((float4*)out)[row] = make_float4(pre[0], pre[1], pre[2], pre[3]);
    ((float4*)(out + (size_t)T_DIM * HCN))[row] =
        make_float4(post[0], post[1], post[2], post[3]);
    float4* res = (float4*)(out + 2 * (size_t)T_DIM * HCN + (size_t)row * 16);
#pragma unroll
    for (int i = 0; i < 4; i++) {
        res[i] = make_float4(u[i] * H[i][0] * v[0], u[i] * H[i][1] * v[1],
                             u[i] * H[i][2] * v[2], u[i] * H[i][3] * v[3]);
    }
}

// ---------------------------------------------------------------------------
// smem: max(staging 12*KT*8 = 49152, reduction 32*16*13*8 + 32*16*4 = 55296)
#define SMEM_BYTES 55296

extern "C" void kernel_launch(void* const* d_in, const int* in_sizes, int n_in,
                              void* d_out, int out_size) {
    const float* x = (const float*)d_in[0];
    const float* w = (const float*)d_in[1];
    const float* bias = (const float*)d_in[2];
    const float* alpha = (const float*)d_in[3];
    float* out = (float*)d_out;

    cudaFuncSetAttribute(mhc_gemm_kernel,
                         cudaFuncAttributeMaxDynamicSharedMemorySize,
                         SMEM_BYTES);

    dim3 grid(T_DIM / MB, KSPLIT);
    mhc_gemm_kernel<<<grid, NTHREADS, SMEM_BYTES>>>(x, w);
    mhc_finish_kernel<<<T_DIM / 32, 32>>>(bias, alpha, out);
}